// round 9
// baseline (speedup 1.0000x reference)
#include <cuda_runtime.h>
#include <math.h>

#define NN 50000
#define MAXE 1000000   // E (800000) + self loops (50000), with margin

// ---------------- device scratch (no allocations allowed) ----------------
__device__ float g_xl1[NN * 256];   // x @ W1          [N,4,64]
__device__ float g_h  [NN * 256];   // layer-1 output (post ELU)
__device__ float g_xl2[NN * 64];    // h @ W2          [N,1,64]
__device__ float g_as1[NN * 4];
__device__ float g_ad1[NN * 4];
__device__ float g_as2[NN];
__device__ float g_ad2[NN];
__device__ int   g_deg[NN];
__device__ int   g_rowptr[NN + 1];
__device__ int   g_cursor[NN];
__device__ int   g_csr[MAXE];       // src node per CSR slot (grouped by dst)
__device__ int   g_is64;

// ---------------- helpers ----------------
__device__ __forceinline__ int edge_at(const void* ei, long long i, int is64) {
    return is64 ? (int)((const long long*)ei)[i] : ((const int*)ei)[i];
}

// ---------------- init ----------------
__global__ void k_init() {
    int i = blockIdx.x * blockDim.x + threadIdx.x;
    if (i < NN) g_deg[i] = 0;
    if (i == 0) g_is64 = 1;
}

// Detect whether edge_index buffer is int64 or int32.
// If data is int32, an int64-view value combines two node ids -> >= 2^32 w.h.p.
__global__ void k_detect(const void* ei, int n_slots) {
    int t = threadIdx.x;
    const long long* p = (const long long*)ei;
    for (int j = t; j < n_slots; j += blockDim.x) {
        long long v = p[j];
        if (v < 0 || v >= NN) { atomicExch(&g_is64, 0); break; }
    }
}

// ---------------- simple tiled SGEMM: C[M,N] = A[M,K] @ B[K,N] ----------------
// 64x64 block tile, BK=16, 256 threads, 4x4 per-thread micro tile.
__global__ void __launch_bounds__(256) k_gemm(
        const float* __restrict__ A, const float* __restrict__ B,
        float* __restrict__ C, int M, int N, int K) {
    __shared__ float As[16][68];   // As[k][m]
    __shared__ float Bs[16][68];   // Bs[k][n]
    int t  = threadIdx.x;
    int tx = t & 15, ty = t >> 4;
    int bm0 = blockIdx.x * 64, bn0 = blockIdx.y * 64;

    int ar  = t >> 2, ac4 = (t & 3) * 4;    // A tile load coords
    int br  = t >> 4, bc4 = (t & 15) * 4;   // B tile load coords

    float acc[4][4] = {};

    for (int kt = 0; kt < K; kt += 16) {
        float4 av = make_float4(0.f, 0.f, 0.f, 0.f);
        int grow = bm0 + ar;
        if (grow < M)
            av = *(const float4*)(A + (size_t)grow * K + kt + ac4);
        As[ac4 + 0][ar] = av.x; As[ac4 + 1][ar] = av.y;
        As[ac4 + 2][ar] = av.z; As[ac4 + 3][ar] = av.w;

        float4 bv = *(const float4*)(B + (size_t)(kt + br) * N + bn0 + bc4);
        *(float4*)&Bs[br][bc4] = bv;
        __syncthreads();

        #pragma unroll
        for (int k = 0; k < 16; k++) {
            float4 a = *(float4*)&As[k][ty * 4];
            float4 b = *(float4*)&Bs[k][tx * 4];
            acc[0][0] += a.x * b.x; acc[0][1] += a.x * b.y; acc[0][2] += a.x * b.z; acc[0][3] += a.x * b.w;
            acc[1][0] += a.y * b.x; acc[1][1] += a.y * b.y; acc[1][2] += a.y * b.z; acc[1][3] += a.y * b.w;
            acc[2][0] += a.z * b.x; acc[2][1] += a.z * b.y; acc[2][2] += a.z * b.z; acc[2][3] += a.z * b.w;
            acc[3][0] += a.w * b.x; acc[3][1] += a.w * b.y; acc[3][2] += a.w * b.z; acc[3][3] += a.w * b.w;
        }
        __syncthreads();
    }

    #pragma unroll
    for (int i = 0; i < 4; i++) {
        int row = bm0 + ty * 4 + i;
        if (row < M) {
            float4 o = make_float4(acc[i][0], acc[i][1], acc[i][2], acc[i][3]);
            *(float4*)(C + (size_t)row * N + bn0 + tx * 4) = o;
        }
    }
}

// ---------------- per-node attention logits, layer 1 (4 heads x 64) ----------------
__global__ void __launch_bounds__(256) k_alpha1(
        const float* __restrict__ asv, const float* __restrict__ adv) {
    int gw = (blockIdx.x * blockDim.x + threadIdx.x) >> 5;
    int lane = threadIdx.x & 31;
    if (gw >= NN) return;
    const float* row = g_xl1 + (size_t)gw * 256;
    float ps[4] = {0.f, 0.f, 0.f, 0.f};
    float pd[4] = {0.f, 0.f, 0.f, 0.f};
    #pragma unroll
    for (int j = 0; j < 8; j++) {
        int col = lane + 32 * j;
        float v = row[col];
        ps[j >> 1] += v * __ldg(asv + col);
        pd[j >> 1] += v * __ldg(adv + col);
    }
    #pragma unroll
    for (int h = 0; h < 4; h++) {
        #pragma unroll
        for (int off = 16; off; off >>= 1) {
            ps[h] += __shfl_xor_sync(0xFFFFFFFFu, ps[h], off);
            pd[h] += __shfl_xor_sync(0xFFFFFFFFu, pd[h], off);
        }
    }
    if (lane == 0) {
        #pragma unroll
        for (int h = 0; h < 4; h++) {
            g_as1[gw * 4 + h] = ps[h];
            g_ad1[gw * 4 + h] = pd[h];
        }
    }
}

// ---------------- per-node attention logits, layer 2 (1 head x 64) ----------------
__global__ void __launch_bounds__(256) k_alpha2(
        const float* __restrict__ asv, const float* __restrict__ adv) {
    int gw = (blockIdx.x * blockDim.x + threadIdx.x) >> 5;
    int lane = threadIdx.x & 31;
    if (gw >= NN) return;
    const float* row = g_xl2 + (size_t)gw * 64;
    float v0 = row[lane], v1 = row[lane + 32];
    float ps = v0 * __ldg(asv + lane) + v1 * __ldg(asv + lane + 32);
    float pd = v0 * __ldg(adv + lane) + v1 * __ldg(adv + lane + 32);
    #pragma unroll
    for (int off = 16; off; off >>= 1) {
        ps += __shfl_xor_sync(0xFFFFFFFFu, ps, off);
        pd += __shfl_xor_sync(0xFFFFFFFFu, pd, off);
    }
    if (lane == 0) { g_as2[gw] = ps; g_ad2[gw] = pd; }
}

// ---------------- CSR build ----------------
__global__ void k_hist(const void* ei, int E) {
    int i = blockIdx.x * blockDim.x + threadIdx.x;
    int Et = E + NN;
    if (i >= Et) return;
    int is64 = g_is64;
    int d = (i < E) ? edge_at(ei, (long long)E + i, is64) : (i - E);
    atomicAdd(&g_deg[d], 1);
}

__global__ void k_scan() {   // single block, 1024 threads
    __shared__ int sums[1024];
    int t = threadIdx.x;
    const int chunk = (NN + 1023) / 1024;
    int lo = t * chunk;
    int hi = lo + chunk; if (hi > NN) hi = NN; if (lo > NN) lo = NN;
    int s = 0;
    for (int i = lo; i < hi; i++) s += g_deg[i];
    sums[t] = s;
    __syncthreads();
    for (int off = 1; off < 1024; off <<= 1) {
        int v = (t >= off) ? sums[t - off] : 0;
        __syncthreads();
        sums[t] += v;
        __syncthreads();
    }
    int run = sums[t] - s;   // exclusive prefix
    for (int i = lo; i < hi; i++) {
        g_rowptr[i] = run;
        g_cursor[i] = run;
        run += g_deg[i];
    }
    if (t == 1023) g_rowptr[NN] = sums[1023];
}

__global__ void k_scatter(const void* ei, int E) {
    int i = blockIdx.x * blockDim.x + threadIdx.x;
    int Et = E + NN;
    if (i >= Et) return;
    int is64 = g_is64;
    int s, d;
    if (i < E) {
        s = edge_at(ei, i, is64);
        d = edge_at(ei, (long long)E + i, is64);
    } else {
        s = d = i - E;
    }
    int pos = atomicAdd(&g_cursor[d], 1);
    g_csr[pos] = s;
}

// ---------------- layer-1 aggregation: warp per dst, online softmax, 4 heads ----------------
__global__ void __launch_bounds__(256) k_agg1(const float* __restrict__ b1) {
    int d = (blockIdx.x * blockDim.x + threadIdx.x) >> 5;
    int lane = threadIdx.x & 31;
    if (d >= NN) return;
    int beg = g_rowptr[d], end = g_rowptr[d + 1];

    float ad[4], m[4], s[4], acc[8];
    const float4 adv = *(const float4*)(g_ad1 + d * 4);
    ad[0] = adv.x; ad[1] = adv.y; ad[2] = adv.z; ad[3] = adv.w;
    #pragma unroll
    for (int h = 0; h < 4; h++) { m[h] = -1e30f; s[h] = 0.f; }
    #pragma unroll
    for (int j = 0; j < 8; j++) acc[j] = 0.f;

    int src_next = (beg < end) ? g_csr[beg] : 0;
    for (int k = beg; k < end; k++) {
        int src = src_next;
        if (k + 1 < end) src_next = g_csr[k + 1];   // prefetch: breaks idx->gather chain
        const float* xr = g_xl1 + (size_t)src * 256;
        const float4 asv = *(const float4*)(g_as1 + src * 4);
        float al[4] = {asv.x, asv.y, asv.z, asv.w};
        float p[4], sc[4];
        #pragma unroll
        for (int h = 0; h < 4; h++) {
            float e = al[h] + ad[h];
            e = e > 0.f ? e : 0.2f * e;          // leaky_relu(0.2)
            if (e > m[h]) { sc[h] = __expf(m[h] - e); p[h] = 1.f; m[h] = e; }
            else          { sc[h] = 1.f; p[h] = __expf(e - m[h]); }
            s[h] = s[h] * sc[h] + p[h];
        }
        #pragma unroll
        for (int j = 0; j < 8; j++) {
            float v = xr[lane + 32 * j];
            acc[j] = acc[j] * sc[j >> 1] + p[j >> 1] * v;
        }
    }
    #pragma unroll
    for (int j = 0; j < 8; j++) {
        int col = lane + 32 * j;
        float o = acc[j] / s[j >> 1] + __ldg(b1 + col);
        o = o > 0.f ? o : (__expf(o) - 1.f);     // ELU
        g_h[(size_t)d * 256 + col] = o;
    }
}

// ---------------- layer-2 aggregation: warp per dst, 1 head, writes d_out ----------------
__global__ void __launch_bounds__(256) k_agg2(
        const float* __restrict__ b2, float* __restrict__ out) {
    int d = (blockIdx.x * blockDim.x + threadIdx.x) >> 5;
    int lane = threadIdx.x & 31;
    if (d >= NN) return;
    int beg = g_rowptr[d], end = g_rowptr[d + 1];
    float ad = g_ad2[d];
    float m = -1e30f, s = 0.f, a0 = 0.f, a1 = 0.f;

    int src_next = (beg < end) ? g_csr[beg] : 0;
    for (int k = beg; k < end; k++) {
        int src = src_next;
        if (k + 1 < end) src_next = g_csr[k + 1];   // prefetch
        float e = g_as2[src] + ad;
        e = e > 0.f ? e : 0.2f * e;
        float p, sc;
        if (e > m) { sc = __expf(m - e); p = 1.f; m = e; }
        else       { sc = 1.f; p = __expf(e - m); }
        s = s * sc + p;
        const float* xr = g_xl2 + (size_t)src * 64;
        a0 = a0 * sc + p * xr[lane];
        a1 = a1 * sc + p * xr[lane + 32];
    }
    out[(size_t)d * 64 + lane]      = a0 / s + __ldg(b2 + lane);
    out[(size_t)d * 64 + lane + 32] = a1 / s + __ldg(b2 + lane + 32);
}

// ---------------- launch ----------------
extern "C" void kernel_launch(void* const* d_in, const int* in_sizes, int n_in,
                              void* d_out, int out_size) {
    const float* x    = (const float*)d_in[0];
    const void*  ei   = d_in[1];
    const float* W1   = (const float*)d_in[2];
    const float* as1v = (const float*)d_in[3];
    const float* ad1v = (const float*)d_in[4];
    const float* b1   = (const float*)d_in[5];
    const float* W2   = (const float*)d_in[6];
    const float* as2v = (const float*)d_in[7];
    const float* ad2v = (const float*)d_in[8];
    const float* b2   = (const float*)d_in[9];

    int E  = in_sizes[1] / 2;
    int Et = E + NN;

    float *p_xl1, *p_h, *p_xl2;
    cudaGetSymbolAddress((void**)&p_xl1, g_xl1);
    cudaGetSymbolAddress((void**)&p_h,   g_h);
    cudaGetSymbolAddress((void**)&p_xl2, g_xl2);

    k_init<<<(NN + 255) / 256, 256>>>();
    int slots = E < 1024 ? E : 1024;
    k_detect<<<1, 256>>>(ei, slots);

    dim3 g1((NN + 63) / 64, 256 / 64);
    k_gemm<<<g1, 256>>>(x, W1, p_xl1, NN, 256, 128);
    k_alpha1<<<(NN * 32 + 255) / 256, 256>>>(as1v, ad1v);

    k_hist<<<(Et + 255) / 256, 256>>>(ei, E);
    k_scan<<<1, 1024>>>();
    k_scatter<<<(Et + 255) / 256, 256>>>(ei, E);

    k_agg1<<<(NN * 32 + 255) / 256, 256>>>(b1);

    dim3 g2((NN + 63) / 64, 1);
    k_gemm<<<g2, 256>>>(p_h, W2, p_xl2, NN, 64, 256);
    k_alpha2<<<(NN * 32 + 255) / 256, 256>>>(as2v, ad2v);

    k_agg2<<<(NN * 32 + 255) / 256, 256>>>(b2, (float*)d_out);
}